// round 4
// baseline (speedup 1.0000x reference)
#include <cuda_runtime.h>
#include <cstdint>

#define D_MODEL 1024
#define N_HEADS 16
#define DK      64
#define SEQ     2048
#define BATCH   2
#define ROWS    (BATCH * SEQ)          /* 4096 */
#define LN_EPS  1e-5f

#define SY ((long long)ROWS * D_MODEL)                         /* 4194304  */
#define SA ((long long)BATCH * N_HEADS * SEQ * SEQ)            /* 134217728 */

// ---------------- scratch (static device globals: no runtime alloc) --------
__device__ float g_q  [ROWS * D_MODEL];
__device__ float g_k  [ROWS * D_MODEL];
__device__ float g_v  [ROWS * D_MODEL];
__device__ float g_ctx[ROWS * D_MODEL];
__device__ float g_o  [ROWS * D_MODEL];

// ---------------- helpers --------------------------------------------------
__device__ __forceinline__ uint32_t f2tf32(float f) {
    uint32_t u;
    asm("cvt.rna.tf32.f32 %0, %1;" : "=r"(u) : "f"(f));
    return u;
}
__device__ __forceinline__ void cp16(void* smem, const void* g) {
    uint32_t a = (uint32_t)__cvta_generic_to_shared(smem);
    asm volatile("cp.async.cg.shared.global [%0], [%1], 16;" :: "r"(a), "l"(g));
}
#define CP_COMMIT()  asm volatile("cp.async.commit_group;")
#define CP_WAIT(n)   asm volatile("cp.async.wait_group %0;" :: "n"(n))

__device__ __forceinline__ void mma_tf32(float c[4],
    uint32_t a0, uint32_t a1, uint32_t a2, uint32_t a3,
    uint32_t b0, uint32_t b1)
{
    asm volatile(
        "mma.sync.aligned.m16n8k8.row.col.f32.tf32.tf32.f32 "
        "{%0,%1,%2,%3}, {%4,%5,%6,%7}, {%8,%9}, {%0,%1,%2,%3};"
        : "+f"(c[0]), "+f"(c[1]), "+f"(c[2]), "+f"(c[3])
        : "r"(a0), "r"(a1), "r"(a2), "r"(a3), "r"(b0), "r"(b1));
}

__device__ __forceinline__ float warpReduceSum(float v) {
#pragma unroll
    for (int o = 16; o > 0; o >>= 1) v += __shfl_xor_sync(0xffffffffu, v, o);
    return v;
}
__device__ __forceinline__ float blockReduceSum(float v) {
    __shared__ float sh[8];
    __shared__ float res;
    int lane = threadIdx.x & 31, w = threadIdx.x >> 5;
    v = warpReduceSum(v);
    if (lane == 0) sh[w] = v;
    __syncthreads();
    if (w == 0) {
        float t = (lane < 8) ? sh[lane] : 0.0f;
        t = warpReduceSum(t);
        if (lane == 0) res = t;
    }
    __syncthreads();
    float r = res;
    __syncthreads();
    return r;
}

// ---------------- tf32 GEMM NT core ---------------------------------------
// C[128 x BN tile at (by,bx)] = alpha * A[M,K] * B[N,K]^T
template<int BN>
__device__ __forceinline__ void gemm_nt_core(
    const float* __restrict__ A, int lda,
    const float* __restrict__ B, int ldb,
    float* __restrict__ C, int ldc, int K, float alpha)
{
    constexpr int BM  = 128;
    constexpr int BK  = 16;
    constexpr int STR = 20;
    constexpr int TNW = BN / 4;
    constexpr int TNT = BN / 32;

    __shared__ float As[2][BM * STR];
    __shared__ float Bs[2][BN * STR];

    int t    = threadIdx.x;
    int w    = t >> 5, lane = t & 31;
    int wm   = w >> 2, wn = w & 3;
    int g    = lane >> 2, tg = lane & 3;

    const float* Ag = A + (long long)(blockIdx.y * BM) * lda;
    const float* Bg = B + (long long)(blockIdx.x * BN) * ldb;

    int lr = t >> 2;
    int lc = (t & 3) * 4;

    float acc[4][TNT][4];
#pragma unroll
    for (int i = 0; i < 4; i++)
#pragma unroll
        for (int j = 0; j < TNT; j++)
#pragma unroll
            for (int q = 0; q < 4; q++) acc[i][j][q] = 0.0f;

    auto load_tile = [&](int kt, int s) {
        long long ko = (long long)kt * BK;
        cp16(&As[s][lr * STR + lc],        Ag + (long long)lr * lda + ko + lc);
        cp16(&As[s][(lr + 64) * STR + lc], Ag + (long long)(lr + 64) * lda + ko + lc);
        cp16(&Bs[s][lr * STR + lc],        Bg + (long long)lr * ldb + ko + lc);
        if (BN == 128)
            cp16(&Bs[s][(lr + 64) * STR + lc], Bg + (long long)(lr + 64) * ldb + ko + lc);
    };

    int KT = K / BK;
    load_tile(0, 0);
    CP_COMMIT();

    for (int kt = 0; kt < KT; kt++) {
        if (kt + 1 < KT) load_tile(kt + 1, (kt + 1) & 1);
        CP_COMMIT();
        CP_WAIT(1);
        __syncthreads();

        const float* as = As[kt & 1];
        const float* bs = Bs[kt & 1];

#pragma unroll
        for (int kh = 0; kh < 2; kh++) {
            int kk = kh * 8;
            uint32_t af[4][4];
#pragma unroll
            for (int i = 0; i < 4; i++) {
                int r = wm * 64 + i * 16 + g;
                af[i][0] = f2tf32(as[r * STR + kk + tg]);
                af[i][1] = f2tf32(as[(r + 8) * STR + kk + tg]);
                af[i][2] = f2tf32(as[r * STR + kk + tg + 4]);
                af[i][3] = f2tf32(as[(r + 8) * STR + kk + tg + 4]);
            }
            uint32_t bf[TNT][2];
#pragma unroll
            for (int j = 0; j < TNT; j++) {
                int n = wn * TNW + j * 8 + g;
                bf[j][0] = f2tf32(bs[n * STR + kk + tg]);
                bf[j][1] = f2tf32(bs[n * STR + kk + tg + 4]);
            }
#pragma unroll
            for (int i = 0; i < 4; i++)
#pragma unroll
                for (int j = 0; j < TNT; j++)
                    mma_tf32(acc[i][j], af[i][0], af[i][1], af[i][2], af[i][3],
                             bf[j][0], bf[j][1]);
        }
        __syncthreads();
    }

#pragma unroll
    for (int i = 0; i < 4; i++) {
        long long r0 = (long long)blockIdx.y * BM + wm * 64 + i * 16 + g;
#pragma unroll
        for (int j = 0; j < TNT; j++) {
            int col = blockIdx.x * BN + wn * TNW + j * 8 + tg * 2;
            float2 lo = make_float2(alpha * acc[i][j][0], alpha * acc[i][j][1]);
            float2 hi = make_float2(alpha * acc[i][j][2], alpha * acc[i][j][3]);
            *(float2*)(C + r0 * ldc + col)       = lo;
            *(float2*)(C + (r0 + 8) * ldc + col) = hi;
        }
    }
}

// ---------------- fused QKV projection (z selects weight/output) -----------
__global__ void __launch_bounds__(256)
qkv_proj(const float* __restrict__ x,
         const float* __restrict__ Wq, const float* __restrict__ Wk,
         const float* __restrict__ Wv,
         float* __restrict__ q, float* __restrict__ k, float* __restrict__ v)
{
    const float* B = (blockIdx.z == 0) ? Wq : (blockIdx.z == 1) ? Wk : Wv;
    float*       C = (blockIdx.z == 0) ? q  : (blockIdx.z == 1) ? k  : v;
    gemm_nt_core<128>(x, D_MODEL, B, D_MODEL, C, D_MODEL, D_MODEL, 1.0f);
}

__global__ void __launch_bounds__(256)
out_proj(const float* __restrict__ ctx, const float* __restrict__ Wo,
         float* __restrict__ o)
{
    gemm_nt_core<128>(ctx, D_MODEL, Wo, D_MODEL, o, D_MODEL, D_MODEL, 1.0f);
}

// ---------------- fused attention core -------------------------------------
// Block = 128 query rows of one (batch,head). Two passes over 16 key tiles:
//   pass 1: S = QK^T/8 -> online row max m, exp-sum l (registers only)
//   pass 2: P = exp(S-m)/l -> smem, -> attn gmem (if needed), ctx += P @ V
// smem: Q[128x68] K[2][128x68] V[128x68] P[128x132] = 206848 B
#define QSTR 68
#define PSTR 132
#define FA_SMEM ((4 * 128 * QSTR + 128 * PSTR) * 4)

__global__ void __launch_bounds__(256)
fused_attn(const float* __restrict__ Qg, const float* __restrict__ Kg,
           const float* __restrict__ Vg, float* __restrict__ ctx,
           float* __restrict__ attn)
{
    extern __shared__ float sm[];
    float* Qs  = sm;
    float* Ks0 = Qs  + 128 * QSTR;
    float* Ks1 = Ks0 + 128 * QSTR;
    float* Vs  = Ks1 + 128 * QSTR;
    float* Ps  = Vs  + 128 * QSTR;

    int bh = blockIdx.y, b = bh >> 4, h = bh & 15;
    int row0 = blockIdx.x * 128;
    const float* qb = Qg + (long long)b * SEQ * D_MODEL + h * DK;
    const float* kb = Kg + (long long)b * SEQ * D_MODEL + h * DK;
    const float* vb = Vg + (long long)b * SEQ * D_MODEL + h * DK;

    int t = threadIdx.x, w = t >> 5, lane = t & 31;
    int g = lane >> 2, tg = lane & 3;
    int wrow = w * 16;

    // full 128x64 f32 tile: 2048 x 16B chunks (8 cp.async per thread)
    auto loadTile = [&](const float* src, float* dst) {
#pragma unroll
        for (int i = t; i < 2048; i += 256) {
            int r = i >> 4, cc = (i & 15) * 4;
            cp16(&dst[r * QSTR + cc], src + (long long)r * D_MODEL + cc);
        }
    };

    // S tile MMA: c[16][4] = Q(warp rows) x K-tile^T
    auto s_mma = [&](const float* Kbuf, float c[16][4]) {
#pragma unroll
        for (int j = 0; j < 16; j++)
#pragma unroll
            for (int q = 0; q < 4; q++) c[j][q] = 0.0f;
#pragma unroll
        for (int ks = 0; ks < 8; ks++) {
            int k0 = ks * 8;
            uint32_t a0 = f2tf32(Qs[(wrow + g) * QSTR + k0 + tg]);
            uint32_t a1 = f2tf32(Qs[(wrow + g + 8) * QSTR + k0 + tg]);
            uint32_t a2 = f2tf32(Qs[(wrow + g) * QSTR + k0 + tg + 4]);
            uint32_t a3 = f2tf32(Qs[(wrow + g + 8) * QSTR + k0 + tg + 4]);
#pragma unroll
            for (int j = 0; j < 16; j++) {
                uint32_t b0 = f2tf32(Kbuf[(j * 8 + g) * QSTR + k0 + tg]);
                uint32_t b1 = f2tf32(Kbuf[(j * 8 + g) * QSTR + k0 + tg + 4]);
                mma_tf32(c[j], a0, a1, a2, a3, b0, b1);
            }
        }
    };

    // ---------------- pass 1: stats ----------------
    float M0 = -1e30f, M1 = -1e30f, L0 = 0.0f, L1 = 0.0f;

    loadTile(qb + (long long)row0 * D_MODEL, Qs);
    loadTile(kb, Ks0);
    CP_COMMIT();

    for (int kt = 0; kt < 16; kt++) {
        __syncthreads();
        if (kt < 15) loadTile(kb + (long long)(kt + 1) * 128 * D_MODEL,
                              ((kt + 1) & 1) ? Ks1 : Ks0);
        CP_COMMIT();
        CP_WAIT(1);
        __syncthreads();

        float c[16][4];
        s_mma((kt & 1) ? Ks1 : Ks0, c);

        float t0 = -1e30f, t1 = -1e30f;
#pragma unroll
        for (int j = 0; j < 16; j++) {
            t0 = fmaxf(t0, fmaxf(c[j][0], c[j][1]));
            t1 = fmaxf(t1, fmaxf(c[j][2], c[j][3]));
        }
        t0 = fmaxf(t0, __shfl_xor_sync(0xffffffffu, t0, 1));
        t0 = fmaxf(t0, __shfl_xor_sync(0xffffffffu, t0, 2));
        t1 = fmaxf(t1, __shfl_xor_sync(0xffffffffu, t1, 1));
        t1 = fmaxf(t1, __shfl_xor_sync(0xffffffffu, t1, 2));

        float nM0 = fmaxf(M0, t0 * 0.125f);
        float nM1 = fmaxf(M1, t1 * 0.125f);
        float s0 = 0.0f, s1 = 0.0f;
#pragma unroll
        for (int j = 0; j < 16; j++) {
            s0 += __expf(c[j][0] * 0.125f - nM0) + __expf(c[j][1] * 0.125f - nM0);
            s1 += __expf(c[j][2] * 0.125f - nM1) + __expf(c[j][3] * 0.125f - nM1);
        }
        s0 += __shfl_xor_sync(0xffffffffu, s0, 1);
        s0 += __shfl_xor_sync(0xffffffffu, s0, 2);
        s1 += __shfl_xor_sync(0xffffffffu, s1, 1);
        s1 += __shfl_xor_sync(0xffffffffu, s1, 2);

        L0 = L0 * __expf(M0 - nM0) + s0;  M0 = nM0;
        L1 = L1 * __expf(M1 - nM1) + s1;  M1 = nM1;
    }
    float invL0 = 1.0f / L0;
    float invL1 = 1.0f / L1;

    // ---------------- pass 2: emit attn + accumulate ctx ----------------
    float d[8][4];
#pragma unroll
    for (int j = 0; j < 8; j++)
#pragma unroll
        for (int q = 0; q < 4; q++) d[j][q] = 0.0f;

    __syncthreads();
    loadTile(kb, Ks0);
    CP_COMMIT();

    for (int kt = 0; kt < 16; kt++) {
        __syncthreads();
        loadTile(vb + (long long)kt * 128 * D_MODEL, Vs);
        if (kt < 15) loadTile(kb + (long long)(kt + 1) * 128 * D_MODEL,
                              ((kt + 1) & 1) ? Ks1 : Ks0);
        CP_COMMIT();
        CP_WAIT(1);
        __syncthreads();

        float c[16][4];
        s_mma((kt & 1) ? Ks1 : Ks0, c);
#pragma unroll
        for (int j = 0; j < 16; j++) {
            c[j][0] = __expf(c[j][0] * 0.125f - M0) * invL0;
            c[j][1] = __expf(c[j][1] * 0.125f - M0) * invL0;
            c[j][2] = __expf(c[j][2] * 0.125f - M1) * invL1;
            c[j][3] = __expf(c[j][3] * 0.125f - M1) * invL1;
        }
        CP_WAIT(0);
        __syncthreads();

#pragma unroll
        for (int j = 0; j < 16; j++) {
            *(float2*)&Ps[(wrow + g) * PSTR + j * 8 + 2 * tg]     = make_float2(c[j][0], c[j][1]);
            *(float2*)&Ps[(wrow + g + 8) * PSTR + j * 8 + 2 * tg] = make_float2(c[j][2], c[j][3]);
        }
        __syncthreads();

        // ctx += P(128x128) @ V(128x64)
#pragma unroll
        for (int ks = 0; ks < 16; ks++) {
            int k0 = ks * 8;
            uint32_t a0 = f2tf32(Ps[(wrow + g) * PSTR + k0 + tg]);
            uint32_t a1 = f2tf32(Ps[(wrow + g + 8) * PSTR + k0 + tg]);
            uint32_t a2 = f2tf32(Ps[(wrow + g) * PSTR + k0 + tg + 4]);
            uint32_t a3 = f2tf32(Ps[(wrow + g + 8) * PSTR + k0 + tg + 4]);
#pragma unroll
            for (int j = 0; j < 8; j++) {
                uint32_t b0 = f2tf32(Vs[(k0 + tg) * QSTR + j * 8 + g]);
                uint32_t b1 = f2tf32(Vs[(k0 + tg + 4) * QSTR + j * 8 + g]);
                mma_tf32(d[j], a0, a1, a2, a3, b0, b1);
            }
        }

        if (attn) {
            float* ap = attn + ((long long)bh * SEQ + row0) * SEQ + (long long)kt * 128;
#pragma unroll
            for (int i = t; i < 4096; i += 256) {
                int r = i >> 5, cc = (i & 31) * 4;
                *(float4*)&ap[(long long)r * SEQ + cc] = *(const float4*)&Ps[r * PSTR + cc];
            }
        }
    }

    // ctx epilogue
    float* cb = ctx + (long long)b * SEQ * D_MODEL + h * DK;
#pragma unroll
    for (int j = 0; j < 8; j++) {
        long long r = row0 + wrow + g;
        *(float2*)&cb[r * D_MODEL + j * 8 + 2 * tg]       = make_float2(d[j][0], d[j][1]);
        *(float2*)&cb[(r + 8) * D_MODEL + j * 8 + 2 * tg] = make_float2(d[j][2], d[j][3]);
    }
}

// ---------------- bias + residual + LayerNorm ------------------------------
__global__ void __launch_bounds__(256)
bias_res_ln(const float* __restrict__ o, const float* __restrict__ x,
            const float* __restrict__ bo, const float* __restrict__ gamma,
            const float* __restrict__ beta, float* __restrict__ y)
{
    long long row = blockIdx.x;
    int tid = threadIdx.x;
    const float4* o4 = (const float4*)(o + row * D_MODEL);
    const float4* x4 = (const float4*)(x + row * D_MODEL);
    const float4* b4 = (const float4*)bo;
    const float4* g4 = (const float4*)gamma;
    const float4* be4 = (const float4*)beta;

    float4 ov = o4[tid], xv = x4[tid], bv = b4[tid];
    float4 v;
    v.x = ov.x + xv.x + bv.x;
    v.y = ov.y + xv.y + bv.y;
    v.z = ov.z + xv.z + bv.z;
    v.w = ov.w + xv.w + bv.w;

    float s  = v.x + v.y + v.z + v.w;
    float sq = v.x * v.x + v.y * v.y + v.z * v.z + v.w * v.w;
    s  = blockReduceSum(s);
    sq = blockReduceSum(sq);

    float mean = s * (1.0f / D_MODEL);
    float var  = sq * (1.0f / D_MODEL) - mean * mean;
    float rstd = rsqrtf(var + LN_EPS);

    float4 gv = g4[tid], bev = be4[tid];
    float4 r;
    r.x = (v.x - mean) * rstd * gv.x + bev.x;
    r.y = (v.y - mean) * rstd * gv.y + bev.y;
    r.z = (v.z - mean) * rstd * gv.z + bev.z;
    r.w = (v.w - mean) * rstd * gv.w + bev.w;
    ((float4*)(y + row * D_MODEL))[tid] = r;
}

// ---------------- launch ---------------------------------------------------
extern "C" void kernel_launch(void* const* d_in, const int* in_sizes, int n_in,
                              void* d_out, int out_size)
{
    const float* x     = (const float*)d_in[0];
    const float* Wq    = (const float*)d_in[1];
    const float* Wk    = (const float*)d_in[2];
    const float* Wv    = (const float*)d_in[3];
    const float* Wo    = (const float*)d_in[4];
    const float* bo    = (const float*)d_in[5];
    const float* gamma = (const float*)d_in[6];
    const float* beta  = (const float*)d_in[7];

    float* y_out    = (float*)d_out;
    float* attn_out = nullptr;
    if ((long long)out_size >= SY + SA) {
        attn_out = y_out + SY;                 // outputs concatenated: y, attn
    } else if ((long long)out_size == SA) {
        attn_out = y_out;                      // attn-only output
        y_out = nullptr;
    }

    float *q, *k, *v, *ctx, *ob;
    cudaGetSymbolAddress((void**)&q,   g_q);
    cudaGetSymbolAddress((void**)&k,   g_k);
    cudaGetSymbolAddress((void**)&v,   g_v);
    cudaGetSymbolAddress((void**)&ctx, g_ctx);
    cudaGetSymbolAddress((void**)&ob,  g_o);

    static int smem_set = 0;
    if (!smem_set) {
        cudaFuncSetAttribute(fused_attn,
            cudaFuncAttributeMaxDynamicSharedMemorySize, FA_SMEM);
        smem_set = 1;
    }

    dim3 blk(256);

    // Q/K/V projections in one launch
    qkv_proj<<<dim3(8, 32, 3), blk>>>(x, Wq, Wk, Wv, q, k, v);

    // fused attention: stats + softmax + attn emit + ctx
    fused_attn<<<dim3(16, 32), blk, FA_SMEM>>>(q, k, v, ctx, attn_out);

    if (y_out) {
        out_proj<<<dim3(8, 32), blk>>>(ctx, Wo, ob);
        bias_res_ln<<<ROWS, blk>>>(ob, x, bo, gamma, beta, y_out);
    }
}